// round 1
// baseline (speedup 1.0000x reference)
#include <cuda_runtime.h>

// Problem shape (fixed by the dataset): Na=Nb=4096, Fa=Fb=512, D=128, E=131072
#define NMAX 4096
#define DV   128

__device__ __align__(16) float g_ha[NMAX * DV];
__device__ __align__(16) float g_hb[NMAX * DV];
__device__ __align__(16) float g_t [NMAX * DV];
__device__ __align__(16) int   g_deg[NMAX];
__device__ int g_mode64;   // 1 if edge indices are int64, 0 if int32

// ---------------------------------------------------------------------------
// Detect int64 vs int32 edge buffers: indices are in [0,4096); if stored as
// little-endian int64, every odd 32-bit word is 0. Sample 2048 words.
// ---------------------------------------------------------------------------
__global__ void detect_kernel(const int* __restrict__ e, int nwords) {
    __shared__ int any;
    if (threadIdx.x == 0) any = 0;
    __syncthreads();
    for (int i = 1 + 2 * threadIdx.x; i < nwords; i += 2 * blockDim.x)
        if (e[i] != 0) any = 1;
    __syncthreads();
    if (threadIdx.x == 0) g_mode64 = (any == 0) ? 1 : 0;
}

// ---------------------------------------------------------------------------
// Zero scratch (t, deg) and the output buffer (poisoned by harness).
// n = Na*D float elements (== Nb*D here).
// ---------------------------------------------------------------------------
__global__ void zero_kernel(float* __restrict__ out, int n) {
    int i = blockIdx.x * blockDim.x + threadIdx.x;
    float4 z = make_float4(0.f, 0.f, 0.f, 0.f);
    int n4 = n >> 2;
    if (i < n4) {
        ((float4*)out)[i] = z;
        ((float4*)g_t)[i] = z;
    }
    if (i < NMAX / 4) ((int4*)g_deg)[i] = make_int4(0, 0, 0, 0);
}

// ---------------------------------------------------------------------------
// h = relu(X @ W + b)    X:[M,K] row-major, W:[K,128] row-major, h:[M,128]
// Tile: 32 rows x 128 cols per block, BK=32, 256 threads, 4x4 per thread.
// ---------------------------------------------------------------------------
__global__ void __launch_bounds__(256) gemm_relu_kernel(
    const float* __restrict__ X, const float* __restrict__ W,
    const float* __restrict__ bias, int K, int which)
{
    constexpr int BM = 32, BN = 128, BK = 32;
    __shared__ float As[BK][BM + 1];
    __shared__ float Bs[BK][BN];

    float* __restrict__ H = which ? g_hb : g_ha;
    const int bm = blockIdx.x * BM;
    const int t  = threadIdx.x;
    const int tx = t & 31;   // column group: cols tx*4 .. tx*4+3
    const int ty = t >> 5;   // row group:    rows ty*4 .. ty*4+3

    float acc[4][4];
#pragma unroll
    for (int i = 0; i < 4; i++)
#pragma unroll
        for (int j = 0; j < 4; j++) acc[i][j] = 0.f;

    for (int k0 = 0; k0 < K; k0 += BK) {
        // A tile 32x32: one float4 per thread, stored transposed
        {
            int r  = t >> 3;
            int c4 = t & 7;
            float4 v = *(const float4*)(X + (size_t)(bm + r) * K + k0 + c4 * 4);
            As[c4 * 4 + 0][r] = v.x;
            As[c4 * 4 + 1][r] = v.y;
            As[c4 * 4 + 2][r] = v.z;
            As[c4 * 4 + 3][r] = v.w;
        }
        // B tile 32x128: 4 float4 per thread
#pragma unroll
        for (int i = 0; i < 4; i++) {
            int idx = t + i * 256;
            int kk  = idx >> 5;
            int c4  = idx & 31;
            float4 v = *(const float4*)(W + (size_t)(k0 + kk) * BN + c4 * 4);
            *(float4*)&Bs[kk][c4 * 4] = v;
        }
        __syncthreads();
#pragma unroll
        for (int kk = 0; kk < BK; kk++) {
            float a0 = As[kk][ty * 4 + 0];
            float a1 = As[kk][ty * 4 + 1];
            float a2 = As[kk][ty * 4 + 2];
            float a3 = As[kk][ty * 4 + 3];
            float4 b = *(float4*)&Bs[kk][tx * 4];
            acc[0][0] += a0 * b.x; acc[0][1] += a0 * b.y; acc[0][2] += a0 * b.z; acc[0][3] += a0 * b.w;
            acc[1][0] += a1 * b.x; acc[1][1] += a1 * b.y; acc[1][2] += a1 * b.z; acc[1][3] += a1 * b.w;
            acc[2][0] += a2 * b.x; acc[2][1] += a2 * b.y; acc[2][2] += a2 * b.z; acc[2][3] += a2 * b.w;
            acc[3][0] += a3 * b.x; acc[3][1] += a3 * b.y; acc[3][2] += a3 * b.z; acc[3][3] += a3 * b.w;
        }
        __syncthreads();
    }

    float4 bv = *(const float4*)(bias + tx * 4);
#pragma unroll
    for (int i = 0; i < 4; i++) {
        int r = bm + ty * 4 + i;
        float4 o;
        o.x = fmaxf(acc[i][0] + bv.x, 0.f);
        o.y = fmaxf(acc[i][1] + bv.y, 0.f);
        o.z = fmaxf(acc[i][2] + bv.z, 0.f);
        o.w = fmaxf(acc[i][3] + bv.w, 0.f);
        *(float4*)(H + (size_t)r * DV + tx * 4) = o;
    }
}

// ---------------------------------------------------------------------------
// deg[k] += (count of edge_ab cols == k) + (count of edge_ba rows == k)
// ---------------------------------------------------------------------------
__global__ void deg_kernel(const int* __restrict__ eab,
                           const int* __restrict__ eba, int E) {
    int i = blockIdx.x * blockDim.x + threadIdx.x;
    if (i >= E) return;
    int s = g_mode64 ? 2 : 1;
    atomicAdd(&g_deg[eab[(size_t)(E + i) * s]], 1);  // edge_ab[1][i]
    atomicAdd(&g_deg[eba[(size_t)i * s]], 1);        // edge_ba[0][i]
}

// ---------------------------------------------------------------------------
// t[row] += h_a[col] for each edge in edge_ba. One warp per edge,
// one red.global.add.v4.f32 (16B) per lane.
// ---------------------------------------------------------------------------
__global__ void scatter1_kernel(const int* __restrict__ e, int E) {
    int gw   = (blockIdx.x * blockDim.x + threadIdx.x) >> 5;
    int lane = threadIdx.x & 31;
    if (gw >= E) return;
    int s   = g_mode64 ? 2 : 1;
    int row = e[(size_t)gw * s];
    int col = e[(size_t)(E + gw) * s];
    float4 v = *(const float4*)(g_ha + (size_t)col * DV + lane * 4);
    float* p = g_t + (size_t)row * DV + lane * 4;
    asm volatile("red.global.add.v4.f32 [%0], {%1,%2,%3,%4};"
                 :: "l"(p), "f"(v.x), "f"(v.y), "f"(v.z), "f"(v.w) : "memory");
}

// ---------------------------------------------------------------------------
// t[i,:] = d(deg[i]) * t[i,:] + h_b[i,:]   (in place)
// ---------------------------------------------------------------------------
__global__ void combine_kernel(int n4) {
    int i = blockIdx.x * blockDim.x + threadIdx.x;
    if (i >= n4) return;
    int row = i >> 5;  // DV/4 = 32 float4 per row
    int deg = g_deg[row];
    float d = deg > 0 ? 1.0f / (float)deg : 0.0f;
    float4 tv = ((float4*)g_t)[i];
    float4 hb = ((float4*)g_hb)[i];
    float4 o;
    o.x = d * tv.x + hb.x;
    o.y = d * tv.y + hb.y;
    o.z = d * tv.z + hb.z;
    o.w = d * tv.w + hb.w;
    ((float4*)g_t)[i] = o;
}

// ---------------------------------------------------------------------------
// out[row] += t[col] for each edge in edge_ab.
// ---------------------------------------------------------------------------
__global__ void scatter2_kernel(const int* __restrict__ e, int E,
                                float* __restrict__ out) {
    int gw   = (blockIdx.x * blockDim.x + threadIdx.x) >> 5;
    int lane = threadIdx.x & 31;
    if (gw >= E) return;
    int s   = g_mode64 ? 2 : 1;
    int row = e[(size_t)gw * s];
    int col = e[(size_t)(E + gw) * s];
    float4 v = *(const float4*)(g_t + (size_t)col * DV + lane * 4);
    float* p = out + (size_t)row * DV + lane * 4;
    asm volatile("red.global.add.v4.f32 [%0], {%1,%2,%3,%4};"
                 :: "l"(p), "f"(v.x), "f"(v.y), "f"(v.z), "f"(v.w) : "memory");
}

// ---------------------------------------------------------------------------
extern "C" void kernel_launch(void* const* d_in, const int* in_sizes, int n_in,
                              void* d_out, int out_size) {
    const float* x_a = (const float*)d_in[0];
    const float* x_b = (const float*)d_in[1];
    const float* W_a = (const float*)d_in[2];
    const float* b_a = (const float*)d_in[3];
    const float* W_b = (const float*)d_in[4];
    const float* b_b = (const float*)d_in[5];
    const int*   eab = (const int*)d_in[6];
    const int*   eba = (const int*)d_in[7];
    float* out = (float*)d_out;

    const int D  = in_sizes[3];          // 128
    const int Fa = in_sizes[2] / D;      // 512
    const int Na = in_sizes[0] / Fa;     // 4096
    const int Fb = in_sizes[4] / D;      // 512
    const int Nb = in_sizes[1] / Fb;     // 4096
    const int E  = in_sizes[6] / 2;      // 131072

    const int nElem = Na * D;            // == Nb * D == out_size

    // 1. dtype detection for edge buffers
    int nw = 2 * E < 2048 ? 2 * E : 2048;
    detect_kernel<<<1, 256>>>(eab, nw);

    // 2. zero t, deg, out
    {
        int n4 = nElem / 4;
        zero_kernel<<<(n4 + 255) / 256, 256>>>(out, nElem);
    }

    // 3. feature projections
    gemm_relu_kernel<<<Na / 32, 256>>>(x_a, W_a, b_a, Fa, 0);
    gemm_relu_kernel<<<Nb / 32, 256>>>(x_b, W_b, b_b, Fb, 1);

    // 4. degree histogram
    deg_kernel<<<(E + 255) / 256, 256>>>(eab, eba, E);

    // 5. t = B @ h_a  (scatter over edge_ba)
    {
        long long thr = (long long)E * 32;
        scatter1_kernel<<<(unsigned)((thr + 255) / 256), 256>>>(eba, E);
    }

    // 6. t = d * t + h_b
    {
        int n4 = nElem / 4;
        combine_kernel<<<(n4 + 255) / 256, 256>>>(n4);
    }

    // 7. out = A @ t  (scatter over edge_ab)
    {
        long long thr = (long long)E * 32;
        scatter2_kernel<<<(unsigned)((thr + 255) / 256), 256>>>(eab, E, out);
    }
}

// round 2
// speedup vs baseline: 1.1842x; 1.1842x over previous
#include <cuda_runtime.h>

// Problem shape (fixed by the dataset): Na=Nb=4096, Fa=Fb=512, D=128, E=131072
#define NMAX 4096
#define DV   128

__device__ __align__(16) float g_ha[NMAX * DV];
__device__ __align__(16) float g_hb[NMAX * DV];
__device__ __align__(16) float g_t [NMAX * DV];
__device__ __align__(16) int   g_deg[NMAX];
__device__ int g_mode64;   // 1 if edge indices are int64, 0 if int32

// ---------------------------------------------------------------------------
// Detect int64 vs int32 edge buffers: indices are in [0,4096); if stored as
// little-endian int64, every odd 32-bit word is 0. Sample 2048 words.
// ---------------------------------------------------------------------------
__global__ void detect_kernel(const int* __restrict__ e, int nwords) {
    __shared__ int any;
    if (threadIdx.x == 0) any = 0;
    __syncthreads();
    for (int i = 1 + 2 * threadIdx.x; i < nwords; i += 2 * blockDim.x)
        if (e[i] != 0) any = 1;
    __syncthreads();
    if (threadIdx.x == 0) g_mode64 = (any == 0) ? 1 : 0;
}

// ---------------------------------------------------------------------------
// Zero scratch (t, deg) and the output buffer (poisoned by harness).
// ---------------------------------------------------------------------------
__global__ void zero_kernel(float* __restrict__ out, int n) {
    int i = blockIdx.x * blockDim.x + threadIdx.x;
    float4 z = make_float4(0.f, 0.f, 0.f, 0.f);
    int n4 = n >> 2;
    if (i < n4) {
        ((float4*)out)[i] = z;
        ((float4*)g_t)[i] = z;
    }
    if (i < NMAX / 4) ((int4*)g_deg)[i] = make_int4(0, 0, 0, 0);
}

// ---------------------------------------------------------------------------
// Fused dual GEMM + bias + relu:
//   g_ha = relu(Xa @ Wa + ba)   (blocks [0, blocksPer))
//   g_hb = relu(Xb @ Wb + bb)   (blocks [blocksPer, 2*blocksPer))
// Tile: BM=64 x BN=128, BK=16, 256 threads, 8x4 per thread.
// Packed fp32x2 FMA (Blackwell), A stored transposed in smem so row-pairs
// come out of LDS.128 already packed as b64.
// ---------------------------------------------------------------------------
__global__ void __launch_bounds__(256) gemm2_relu_kernel(
    const float* __restrict__ Xa, const float* __restrict__ Wa, const float* __restrict__ ba,
    const float* __restrict__ Xb, const float* __restrict__ Wb, const float* __restrict__ bb,
    int K, int blocksPer)
{
    constexpr int BM = 64, BN = 128, BK = 16;
    __shared__ float As[2][BK][68];    // [kk][row], pad 68 keeps 16B align + tames STS conflicts
    __shared__ float Bs[2][BK][BN];    // [kk][col]

    const int which = (blockIdx.x >= blocksPer) ? 1 : 0;
    const float* __restrict__ X    = which ? Xb : Xa;
    const float* __restrict__ W    = which ? Wb : Wa;
    const float* __restrict__ bias = which ? bb : ba;
    float* __restrict__ H          = which ? g_hb : g_ha;

    const int bm = (blockIdx.x - which * blocksPer) * BM;
    const int t  = threadIdx.x;
    const int tx = t & 31;        // col group: cols tx*4 .. tx*4+3
    const int ty = t >> 5;        // row group: rows ty*8 .. ty*8+7

    // A-tile load map: one float4 per thread
    const int rowA = t >> 2;      // 0..63
    const int c4A  = t & 3;       // k-subgroup 0..3 (covers kk c4A*4..+3)
    // B-tile load map: two float4 per thread
    const int kkB0 = t >> 5;      // 0..7
    const int c4B  = t & 31;
    // kkB1 = kkB0 + 8

    const int nT = K / BK;        // 32

    // accumulators: 4 row-pairs x 4 cols of packed f32x2 (low=even row, high=odd row)
    unsigned long long acc[4][4];
#pragma unroll
    for (int p = 0; p < 4; p++)
#pragma unroll
        for (int j = 0; j < 4; j++) acc[p][j] = 0ULL;

    const float* Aptr = X + (size_t)(bm + rowA) * K + c4A * 4;
    const float* Bptr0 = W + (size_t)kkB0 * BN + c4B * 4;
    const float* Bptr1 = W + (size_t)(kkB0 + 8) * BN + c4B * 4;

    // preload tile 0
    float4 av  = *(const float4*)(Aptr);
    float4 bv0 = *(const float4*)(Bptr0);
    float4 bv1 = *(const float4*)(Bptr1);

    // store tile 0 (A transposed)
    As[0][c4A * 4 + 0][rowA] = av.x;
    As[0][c4A * 4 + 1][rowA] = av.y;
    As[0][c4A * 4 + 2][rowA] = av.z;
    As[0][c4A * 4 + 3][rowA] = av.w;
    *(float4*)&Bs[0][kkB0][c4B * 4]     = bv0;
    *(float4*)&Bs[0][kkB0 + 8][c4B * 4] = bv1;
    __syncthreads();

    int cur = 0;
    for (int tt = 0; tt < nT; tt++) {
        // prefetch tile tt+1 into registers (issued before the compute uses them)
        if (tt + 1 < nT) {
            int k0n = (tt + 1) * BK;
            av  = *(const float4*)(Aptr + k0n);
            bv0 = *(const float4*)(Bptr0 + (size_t)k0n * BN);
            bv1 = *(const float4*)(Bptr1 + (size_t)k0n * BN);
        }

        // compute current tile
#pragma unroll
        for (int kk = 0; kk < BK; kk++) {
            // 8 A rows as 2 broadcast LDS.128 -> 4 packed row-pairs
            ulonglong2 a01 = *(const ulonglong2*)&As[cur][kk][ty * 8];
            ulonglong2 a23 = *(const ulonglong2*)&As[cur][kk][ty * 8 + 4];
            float4 b = *(const float4*)&Bs[cur][kk][tx * 4];
            unsigned long long B0, B1, B2, B3;
            asm("mov.b64 %0, {%1, %1};" : "=l"(B0) : "f"(b.x));
            asm("mov.b64 %0, {%1, %1};" : "=l"(B1) : "f"(b.y));
            asm("mov.b64 %0, {%1, %1};" : "=l"(B2) : "f"(b.z));
            asm("mov.b64 %0, {%1, %1};" : "=l"(B3) : "f"(b.w));
            unsigned long long ap[4] = {a01.x, a01.y, a23.x, a23.y};
#pragma unroll
            for (int p = 0; p < 4; p++) {
                asm("fma.rn.f32x2 %0, %1, %2, %0;" : "+l"(acc[p][0]) : "l"(ap[p]), "l"(B0));
                asm("fma.rn.f32x2 %0, %1, %2, %0;" : "+l"(acc[p][1]) : "l"(ap[p]), "l"(B1));
                asm("fma.rn.f32x2 %0, %1, %2, %0;" : "+l"(acc[p][2]) : "l"(ap[p]), "l"(B2));
                asm("fma.rn.f32x2 %0, %1, %2, %0;" : "+l"(acc[p][3]) : "l"(ap[p]), "l"(B3));
            }
        }

        // stage tile tt+1 into the other buffer
        if (tt + 1 < nT) {
            int nxt = cur ^ 1;
            As[nxt][c4A * 4 + 0][rowA] = av.x;
            As[nxt][c4A * 4 + 1][rowA] = av.y;
            As[nxt][c4A * 4 + 2][rowA] = av.z;
            As[nxt][c4A * 4 + 3][rowA] = av.w;
            *(float4*)&Bs[nxt][kkB0][c4B * 4]     = bv0;
            *(float4*)&Bs[nxt][kkB0 + 8][c4B * 4] = bv1;
        }
        __syncthreads();
        cur ^= 1;
    }

    // epilogue: unpack, bias, relu, store
    float4 bvb = *(const float4*)(bias + tx * 4);
#pragma unroll
    for (int p = 0; p < 4; p++) {
        float lo[4], hi[4];
#pragma unroll
        for (int j = 0; j < 4; j++) {
            float l, h;
            asm("mov.b64 {%0, %1}, %2;" : "=f"(l), "=f"(h) : "l"(acc[p][j]));
            lo[j] = l; hi[j] = h;
        }
        int r0 = bm + ty * 8 + 2 * p;
        float4 o0, o1;
        o0.x = fmaxf(lo[0] + bvb.x, 0.f); o0.y = fmaxf(lo[1] + bvb.y, 0.f);
        o0.z = fmaxf(lo[2] + bvb.z, 0.f); o0.w = fmaxf(lo[3] + bvb.w, 0.f);
        o1.x = fmaxf(hi[0] + bvb.x, 0.f); o1.y = fmaxf(hi[1] + bvb.y, 0.f);
        o1.z = fmaxf(hi[2] + bvb.z, 0.f); o1.w = fmaxf(hi[3] + bvb.w, 0.f);
        *(float4*)(H + (size_t)r0 * DV + tx * 4)       = o0;
        *(float4*)(H + (size_t)(r0 + 1) * DV + tx * 4) = o1;
    }
}

// ---------------------------------------------------------------------------
// deg[k] += (count of edge_ab cols == k) + (count of edge_ba rows == k)
// ---------------------------------------------------------------------------
__global__ void deg_kernel(const int* __restrict__ eab,
                           const int* __restrict__ eba, int E) {
    int i = blockIdx.x * blockDim.x + threadIdx.x;
    if (i >= E) return;
    int s = g_mode64 ? 2 : 1;
    atomicAdd(&g_deg[eab[(size_t)(E + i) * s]], 1);  // edge_ab[1][i]
    atomicAdd(&g_deg[eba[(size_t)i * s]], 1);        // edge_ba[0][i]
}

// ---------------------------------------------------------------------------
// t[row] += h_a[col] for each edge in edge_ba. One warp per edge,
// one red.global.add.v4.f32 (16B) per lane.
// ---------------------------------------------------------------------------
__global__ void scatter1_kernel(const int* __restrict__ e, int E) {
    int gw   = (blockIdx.x * blockDim.x + threadIdx.x) >> 5;
    int lane = threadIdx.x & 31;
    if (gw >= E) return;
    int s   = g_mode64 ? 2 : 1;
    int row = e[(size_t)gw * s];
    int col = e[(size_t)(E + gw) * s];
    float4 v = *(const float4*)(g_ha + (size_t)col * DV + lane * 4);
    float* p = g_t + (size_t)row * DV + lane * 4;
    asm volatile("red.global.add.v4.f32 [%0], {%1,%2,%3,%4};"
                 :: "l"(p), "f"(v.x), "f"(v.y), "f"(v.z), "f"(v.w) : "memory");
}

// ---------------------------------------------------------------------------
// t[i,:] = d(deg[i]) * t[i,:] + h_b[i,:]   (in place)
// ---------------------------------------------------------------------------
__global__ void combine_kernel(int n4) {
    int i = blockIdx.x * blockDim.x + threadIdx.x;
    if (i >= n4) return;
    int row = i >> 5;  // DV/4 = 32 float4 per row
    int deg = g_deg[row];
    float d = deg > 0 ? 1.0f / (float)deg : 0.0f;
    float4 tv = ((float4*)g_t)[i];
    float4 hb = ((float4*)g_hb)[i];
    float4 o;
    o.x = d * tv.x + hb.x;
    o.y = d * tv.y + hb.y;
    o.z = d * tv.z + hb.z;
    o.w = d * tv.w + hb.w;
    ((float4*)g_t)[i] = o;
}

// ---------------------------------------------------------------------------
// out[row] += t[col] for each edge in edge_ab.
// ---------------------------------------------------------------------------
__global__ void scatter2_kernel(const int* __restrict__ e, int E,
                                float* __restrict__ out) {
    int gw   = (blockIdx.x * blockDim.x + threadIdx.x) >> 5;
    int lane = threadIdx.x & 31;
    if (gw >= E) return;
    int s   = g_mode64 ? 2 : 1;
    int row = e[(size_t)gw * s];
    int col = e[(size_t)(E + gw) * s];
    float4 v = *(const float4*)(g_t + (size_t)col * DV + lane * 4);
    float* p = out + (size_t)row * DV + lane * 4;
    asm volatile("red.global.add.v4.f32 [%0], {%1,%2,%3,%4};"
                 :: "l"(p), "f"(v.x), "f"(v.y), "f"(v.z), "f"(v.w) : "memory");
}

// ---------------------------------------------------------------------------
extern "C" void kernel_launch(void* const* d_in, const int* in_sizes, int n_in,
                              void* d_out, int out_size) {
    const float* x_a = (const float*)d_in[0];
    const float* x_b = (const float*)d_in[1];
    const float* W_a = (const float*)d_in[2];
    const float* b_a = (const float*)d_in[3];
    const float* W_b = (const float*)d_in[4];
    const float* b_b = (const float*)d_in[5];
    const int*   eab = (const int*)d_in[6];
    const int*   eba = (const int*)d_in[7];
    float* out = (float*)d_out;

    const int D  = in_sizes[3];          // 128
    const int Fa = in_sizes[2] / D;      // 512
    const int Na = in_sizes[0] / Fa;     // 4096
    const int Fb = in_sizes[4] / D;      // 512
    const int E  = in_sizes[6] / 2;      // 131072

    const int nElem = Na * D;

    // 1. dtype detection for edge buffers
    int nw = 2 * E < 2048 ? 2 * E : 2048;
    detect_kernel<<<1, 256>>>(eab, nw);

    // 2. zero t, deg, out
    {
        int n4 = nElem / 4;
        zero_kernel<<<(n4 + 255) / 256, 256>>>(out, nElem);
    }

    // 3. fused feature projections (both GEMMs in one launch, 1 wave)
    {
        int blocksPer = Na / 64;   // 64
        gemm2_relu_kernel<<<2 * blocksPer, 256>>>(x_a, W_a, b_a, x_b, W_b, b_b, Fa, blocksPer);
    }

    // 4. degree histogram
    deg_kernel<<<(E + 255) / 256, 256>>>(eab, eba, E);

    // 5. t = B @ h_a  (scatter over edge_ba)
    {
        long long thr = (long long)E * 32;
        scatter1_kernel<<<(unsigned)((thr + 255) / 256), 256>>>(eba, E);
    }

    // 6. t = d * t + h_b
    {
        int n4 = nElem / 4;
        combine_kernel<<<(n4 + 255) / 256, 256>>>(n4);
    }

    // 7. out = A @ t  (scatter over edge_ab)
    {
        long long thr = (long long)E * 32;
        scatter2_kernel<<<(unsigned)((thr + 255) / 256), 256>>>(eab, E, out);
    }
}